// round 11
// baseline (speedup 1.0000x reference)
#include <cuda_runtime.h>
#include <cstdint>
#include <cstddef>

#define T_TOT 8192
#define MULT  512
#define OUTW  8192
#define VROW  1536

#define BT 32
#define BW 128
#define NTHR 256
#define NITER 32                      // k-chunk = 16

#define A_STAGE_W (3*BT*16)           // 1536 words
#define B_STAGE_W (BW*16)             // 2048 words
#define STAGE_W   (A_STAGE_W + B_STAGE_W)   // 3584 words = 14336 B
#define NSTAGE 4
#define DYN_SMEM  (NSTAGE*STAGE_W*4)  // 57344 B/CTA -> 3 CTAs/SM

#define VPLANE (T_TOT*MULT)

// ---- scratch (static device globals: allowed; no runtime allocation)
__device__ uint32_t g_Vd[3u * VPLANE];        // tf32 bits, [i][t][perm word]
__device__ uint32_t g_W1t[MULT * MULT];       // tf32 bits, [n][perm word]

static __device__ __forceinline__ uint32_t smem_u32(const void* p) {
    uint32_t r;
    asm("{ .reg .u64 t; cvta.to.shared.u64 t, %1; cvt.u32.u64 %0, t; }" : "=r"(r) : "l"(p));
    return r;
}
static __device__ __forceinline__ uint32_t f2tf(float x) {
    uint32_t r; asm("cvt.rna.tf32.f32 %0, %1;" : "=r"(r) : "f"(x)); return r;
}
static __device__ __forceinline__ void cpa16(uint32_t dst, const void* src) {
    asm volatile("cp.async.cg.shared.global [%0], [%1], 16;" :: "r"(dst), "l"(src));
}
static __device__ __forceinline__ void mma8(float* c, const uint32_t* a, const uint32_t* b) {
    asm volatile(
        "mma.sync.aligned.m16n8k8.row.col.f32.tf32.tf32.f32 "
        "{%0,%1,%2,%3},{%4,%5,%6,%7},{%8,%9},{%0,%1,%2,%3};\n"
        : "+f"(c[0]), "+f"(c[1]), "+f"(c[2]), "+f"(c[3])
        : "r"(a[0]), "r"(a[1]), "r"(a[2]), "r"(a[3]),
          "r"(b[0]), "r"(b[1]));
}

// Scratch word layout within each 16-word k-block, for matrix row `row`:
//   u16 = 8*g2 + 4*h + c  ->  w16 = 4*c + 2*((g2 + ((row>>1)&1)) & 1) + h

// ---- merged pre-kernel: blocks [0,2048) de-interleave V; blocks [2048,2176) transpose W1
__global__ void __launch_bounds__(512, 2)
pre_all(const float* __restrict__ V, const float* __restrict__ W1) {
    __shared__ float sbuf[4 * VROW];              // V: 4 token rows; W: aliased 2 tiles
    const int tid = threadIdx.x;

    if (blockIdx.x < 2048) {
        // ---- V part: [t][3u+i] -> g_Vd[i][t][blk*16 + w16], STG.64 pairs (h=0,1)
        const int r0 = blockIdx.x * 4;
        const float4* v4 = reinterpret_cast<const float4*>(V) + (size_t)r0 * 384;
#pragma unroll
        for (int k = 0; k < 3; k++) {
            const int c = tid + k * 512;
            const float4 d = v4[c];
            float* sp = sbuf + 4 * c;
            sp[0] = d.x; sp[1] = d.y; sp[2] = d.z; sp[3] = d.w;
        }
        __syncthreads();
        const int half = tid >> 8;                 // rows {0,1} or {2,3}
        const int P = tid & 255;
        const int blk = P >> 3, g2 = (P >> 2) & 1, c = P & 3;
        const int u1 = blk * 16 + g2 * 8 + c;      // h=0; u2 = u1 + 4
#pragma unroll
        for (int rr2 = 0; rr2 < 2; rr2++) {
            const int r = half * 2 + rr2;
            const int t = r0 + r;
            const int w = blk * 16 + 4 * c + 2 * ((g2 + ((t >> 1) & 1)) & 1);
            const float* sp = sbuf + r * VROW + 3 * u1;
            const size_t o = (size_t)t * 512 + w;
            *(uint2*)&g_Vd[o]              = make_uint2(f2tf(sp[0]), f2tf(sp[12]));
            *(uint2*)&g_Vd[o + VPLANE]     = make_uint2(f2tf(sp[1]), f2tf(sp[13]));
            *(uint2*)&g_Vd[o + 2 * VPLANE] = make_uint2(f2tf(sp[2]), f2tf(sp[14]));
        }
    } else {
        // ---- W part: W1 [u][n] -> g_W1t[n][perm word], 2 tiles per block
        float (*wt)[32][33] = reinterpret_cast<float (*)[32][33]>(sbuf);
        const int th = tid >> 8;                   // which tile
        const int t256 = tid & 255;
        const int tx = t256 & 31, ty = t256 >> 5;  // (32, 8)
        const int tile = (blockIdx.x - 2048) * 2 + th;
        const int bn = (tile & 15) * 32, bu = (tile >> 4) * 32;
#pragma unroll
        for (int j = 0; j < 32; j += 8)
            wt[th][ty + j][tx] = W1[(size_t)(bu + ty + j) * MULT + bn + tx];
        __syncthreads();
#pragma unroll
        for (int j = 0; j < 32; j += 8) {
            const int n = bn + ty + j;
            const int u = bu + tx;
            const int blk = u >> 4, g2 = (u >> 3) & 1, h = (u >> 2) & 1, c = u & 3;
            const int w = blk * 16 + 4 * c + 2 * ((g2 + ((n >> 1) & 1)) & 1) + h;
            g_W1t[(size_t)n * 512 + w] = f2tf(wt[th][tx][ty + j]);
        }
    }
}

// ---- main fused kernel: CTA tile 32x128, warp tile 16x32x3, 256 thr, 3 CTAs/SM
__global__ void __launch_bounds__(NTHR, 3)
fused(const float* __restrict__ S, const float* __restrict__ W0,
      float* __restrict__ out)
{
    extern __shared__ uint32_t dsm[];
    __shared__ float sS[96];
    __shared__ float sW0[384];

    const int tid  = threadIdx.x;
    const int lane = tid & 31;
    const int wid  = tid >> 5;
    const int q  = lane >> 2;          // 0..7
    const int rr = lane & 3;           // 0..3
    const int warp_t = wid >> 2;       // 0..1 -> rows warp_t*16
    const int warp_w = wid & 3;        // 0..3 -> cols warp_w*32
    const int bx = blockIdx.x, by = blockIdx.y;
    const int tt0 = by * BT, w0 = bx * BW;

    if (tid < 96) sS[tid] = S[(size_t)tt0 * 3 + tid];
    sW0[tid] = W0[(tid >> 7) * 512 + w0 + (tid & 127)];
    if (tid < 128) sW0[256 + tid] = W0[1024 + w0 + tid];

    // ---- chunk-linear staging: chunk c -> dst word 4c; 896 chunks total
    //      c<384: A plane i=c>>7, row r=(c&127)>>2, j=c&3
    //      c>=384: B row n=(c-384)>>2, j=(c-384)&3
    const uint32_t smem0 = smem_u32(dsm);
    uint32_t sDst[4]; const uint32_t* sSrc[4];
#pragma unroll
    for (int s = 0; s < 4; s++) {
        const int c = (s < 3) ? (tid + s * NTHR) : (768 + tid);   // tid<128 only for s=3
        sDst[s] = smem0 + 16 * c;
        if (c < 384) {
            const int i = c >> 7, r = (c & 127) >> 2, j = c & 3;
            sSrc[s] = g_Vd + (size_t)i * VPLANE + (size_t)(tt0 + r) * 512 + 4 * j;
        } else {
            const int n = (c - 384) >> 2, j = (c - 384) & 3;
            sSrc[s] = g_W1t + (size_t)(w0 + n) * 512 + 4 * j;
        }
    }
    const bool has4 = (tid < 128);

#define STAGE(K, BUF) do {                                                   \
        const uint32_t off_ = (BUF) * (STAGE_W * 4);                         \
        const int kw_ = (K) * 16;                                            \
        cpa16(sDst[0] + off_, sSrc[0] + kw_);                                \
        cpa16(sDst[1] + off_, sSrc[1] + kw_);                                \
        cpa16(sDst[2] + off_, sSrc[2] + kw_);                                \
        if (has4) cpa16(sDst[3] + off_, sSrc[3] + kw_);                      \
        asm volatile("cp.async.commit_group;" ::: "memory");                 \
    } while (0)

    float acc[3][4][4];
#pragma unroll
    for (int i = 0; i < 3; i++)
#pragma unroll
        for (int n = 0; n < 4; n++)
#pragma unroll
            for (int r = 0; r < 4; r++) acc[i][n][r] = 0.f;

    STAGE(0, 0);
    STAGE(1, 1);
    STAGE(2, 2);

    float4* out4 = reinterpret_cast<float4*>(out);
    const float4 zq = make_float4(0.f, 0.f, 0.f, 0.f);

    const int aline0 = (warp_t * 16 + q) * 16;     // A row base (16 words per row)
    const int bline0 = (warp_w * 32 + q) * 16;     // B row base
    const int qpar = (q >> 1) & 1;

    for (int it = 0; it < NITER; ++it) {
        const int buf = it & 3;
        const int rem = NITER - 1 - it;
        if (rem >= 2)      asm volatile("cp.async.wait_group 2;" ::: "memory");
        else if (rem == 1) asm volatile("cp.async.wait_group 1;" ::: "memory");
        else               asm volatile("cp.async.wait_group 0;" ::: "memory");
        __syncthreads();

        if (it + 3 < NITER) STAGE(it + 3, (it + 3) & 3);

        // ---- stream the exact-zero block: 2 rows per even iteration
        if ((it & 1) == 0) {
            const int idx = tid * 3;
            const int r = it + (idx >> 9);         // idx/512... rows: it + idx/384
            const int rr0 = it + idx / 384;
            const int cc = idx % 384;
            float4* zp = out4 + (size_t)(tt0 + rr0) * 2048 + 512 + 384 * bx + cc;
            zp[0] = zq; zp[1] = zq; zp[2] = zq;
            (void)r;
        }

        // ---- compute 2 k8-steps (all LDS.64 conflict-free)
        const uint32_t* sA = dsm + buf * STAGE_W;
        const uint32_t* sB = sA + A_STAGE_W;
#pragma unroll
        for (int g2 = 0; g2 < 2; g2++) {
            const int koff = 4 * rr + 2 * ((g2 + qpar) & 1);
            uint32_t b[4][2];
#pragma unroll
            for (int nt = 0; nt < 4; nt++) {
                const uint2 bb = *reinterpret_cast<const uint2*>(
                    &sB[bline0 + nt * 128 + koff]);
                b[nt][0] = bb.x; b[nt][1] = bb.y;
            }
#pragma unroll
            for (int i = 0; i < 3; i++) {
                const uint32_t* ap = sA + i * 512 + aline0 + koff;
                const uint2 alo = *reinterpret_cast<const uint2*>(ap);        // row q
                const uint2 ahi = *reinterpret_cast<const uint2*>(ap + 128);  // row q+8
                uint32_t a[4] = {alo.x, ahi.x, alo.y, ahi.y};
#pragma unroll
                for (int nt = 0; nt < 4; nt++) mma8(acc[i][nt], a, b[nt]);
            }
        }
    }

    // ---- epilogue: out1 (1o->1o), interleaved layout, vectorized float2
    const float sc = 0.04419417382415922f;  // 1/sqrt(512)
    {
        const int r  = tt0 + warp_t * 16 + q;
        const int wc = w0 + warp_w * 32 + 2 * rr;
#pragma unroll
        for (int nt = 0; nt < 4; nt++) {
            const int w = wc + nt * 8;
            float* p  = out + (size_t)r * OUTW + 512 + 3 * w;
            float* p2 = p + (size_t)8 * OUTW;
            float2 v;
            v = make_float2(acc[0][nt][0] * sc, acc[1][nt][0] * sc); *reinterpret_cast<float2*>(p + 0) = v;
            v = make_float2(acc[2][nt][0] * sc, acc[0][nt][1] * sc); *reinterpret_cast<float2*>(p + 2) = v;
            v = make_float2(acc[1][nt][1] * sc, acc[2][nt][1] * sc); *reinterpret_cast<float2*>(p + 4) = v;
            v = make_float2(acc[0][nt][2] * sc, acc[1][nt][2] * sc); *reinterpret_cast<float2*>(p2 + 0) = v;
            v = make_float2(acc[2][nt][2] * sc, acc[0][nt][3] * sc); *reinterpret_cast<float2*>(p2 + 2) = v;
            v = make_float2(acc[1][nt][3] * sc, acc[2][nt][3] * sc); *reinterpret_cast<float2*>(p2 + 4) = v;
        }
    }

    // ---- epilogue: out0 (0e->0e), cols [w0, w0+128)
    {
        const float k3 = 0.5773502691896258f;  // 1/sqrt(3)
        const int r  = tid >> 3;               // 0..31
        const int cb = (tid & 7) * 16;
        const float s0 = sS[r * 3 + 0], s1 = sS[r * 3 + 1], s2 = sS[r * 3 + 2];
        float* po = out + (size_t)(tt0 + r) * OUTW + w0 + cb;
#pragma unroll
        for (int jj = 0; jj < 16; jj += 4) {
            float4 v;
            v.x = (s0 * sW0[cb + jj + 0] + s1 * sW0[128 + cb + jj + 0] + s2 * sW0[256 + cb + jj + 0]) * k3;
            v.y = (s0 * sW0[cb + jj + 1] + s1 * sW0[128 + cb + jj + 1] + s2 * sW0[256 + cb + jj + 1]) * k3;
            v.z = (s0 * sW0[cb + jj + 2] + s1 * sW0[128 + cb + jj + 2] + s2 * sW0[256 + cb + jj + 2]) * k3;
            v.w = (s0 * sW0[cb + jj + 3] + s1 * sW0[128 + cb + jj + 3] + s2 * sW0[256 + cb + jj + 3]) * k3;
            *reinterpret_cast<float4*>(po + jj) = v;
        }
    }
}

extern "C" void kernel_launch(void* const* d_in, const int* in_sizes, int n_in,
                              void* d_out, int out_size) {
    const float* V  = nullptr;   // vectors [4,2048,1536] = 12582912
    const float* S  = nullptr;   // scalars [4,2048,3]    = 24576
    const float* W0 = nullptr;   // [3,512]               = 1536
    const float* W1 = nullptr;   // [512,512]             = 262144
    for (int i = 0; i < n_in; i++) {
        switch (in_sizes[i]) {
            case 12582912: V  = (const float*)d_in[i]; break;
            case 24576:    S  = (const float*)d_in[i]; break;
            case 1536:     W0 = (const float*)d_in[i]; break;
            case 262144:   W1 = (const float*)d_in[i]; break;
            default: break;
        }
    }
    float* out = (float*)d_out;

    pre_all<<<2176, 512>>>(V, W1);

    cudaFuncSetAttribute(fused, cudaFuncAttributeMaxDynamicSharedMemorySize, DYN_SMEM);
    dim3 grid(MULT / BW, T_TOT / BT);   // (4, 256) = 1024 CTAs
    fused<<<grid, NTHR, DYN_SMEM>>>(S, W0, out);
}

// round 12
// speedup vs baseline: 1.2440x; 1.2440x over previous
#include <cuda_runtime.h>
#include <cstdint>
#include <cstddef>

#define T_TOT 8192
#define MULT  512
#define OUTW  8192
#define VROW  1536

#define BT 32
#define BW 128
#define NTHR 256
#define NITER 16

#define A_STAGE_W (3*BT*32)           // 3072 words
#define B_STAGE_W (BW*32)             // 4096 words
#define STAGE_W   (A_STAGE_W + B_STAGE_W)   // 7168
#define NSTAGE 3
#define DYN_SMEM  (NSTAGE*STAGE_W*4)  // 86016 bytes -> 2 CTAs/SM

#define VPLANE (T_TOT*MULT)

// ---- scratch (static device globals: allowed; no runtime allocation)
__device__ uint32_t g_Vd[3u * VPLANE];        // tf32 bits, [i][t][perm word]
__device__ uint32_t g_W1t[MULT * MULT];       // tf32 bits, [n][perm word]

static __device__ __forceinline__ uint32_t smem_u32(const void* p) {
    uint32_t r;
    asm("{ .reg .u64 t; cvta.to.shared.u64 t, %1; cvt.u32.u64 %0, t; }" : "=r"(r) : "l"(p));
    return r;
}
static __device__ __forceinline__ uint32_t f2tf(float x) {
    uint32_t r; asm("cvt.rna.tf32.f32 %0, %1;" : "=r"(r) : "f"(x)); return r;
}
// conflict-free stored word for logical u (within 32-chunk) at matrix row `row`:
//   u = 8*g + 4*h + c  ->  word = 8*c + 2*((g + row) & 3) + h
static __device__ __forceinline__ int permw(int uu, int row) {
    const int g = uu >> 3, h = (uu >> 2) & 1, c = uu & 3;
    return 8 * c + 2 * ((g + row) & 3) + h;
}
static __device__ __forceinline__ void cpa16(uint32_t dst, const void* src) {
    asm volatile("cp.async.cg.shared.global [%0], [%1], 16;" :: "r"(dst), "l"(src));
}
static __device__ __forceinline__ void mma8(float* c, const uint32_t* a, const uint32_t* b) {
    asm volatile(
        "mma.sync.aligned.m16n8k8.row.col.f32.tf32.tf32.f32 "
        "{%0,%1,%2,%3},{%4,%5,%6,%7},{%8,%9},{%0,%1,%2,%3};\n"
        : "+f"(c[0]), "+f"(c[1]), "+f"(c[2]), "+f"(c[3])
        : "r"(a[0]), "r"(a[1]), "r"(a[2]), "r"(a[3]),
          "r"(b[0]), "r"(b[1]));
}

// ---- merged pre-kernel: blocks [0,2048) de-interleave V; blocks [2048,2176) transpose W1
__global__ void __launch_bounds__(512, 2)
pre_all(const float* __restrict__ V, const float* __restrict__ W1) {
    __shared__ float sbuf[4 * VROW];              // V: 4 token rows; W: aliased 2 tiles
    const int tid = threadIdx.x;

    if (blockIdx.x < 2048) {
        // ---- V part: [t][3u+i] -> g_Vd[i][t][chunk*32 + permw], STG.64 pairs
        const int r0 = blockIdx.x * 4;
        const float4* v4 = reinterpret_cast<const float4*>(V) + (size_t)r0 * 384;
#pragma unroll
        for (int k = 0; k < 3; k++) {
            const int c = tid + k * 512;
            const float4 d = v4[c];
            float* sp = sbuf + 4 * c;
            sp[0] = d.x; sp[1] = d.y; sp[2] = d.z; sp[3] = d.w;
        }
        __syncthreads();
        const int half = tid >> 8;                 // 0..1 -> rows {0,1} or {2,3}
        const int P = tid & 255;                   // pair id
        const int c32 = P >> 4, g = (P >> 2) & 3, c = P & 3;
        const int u1 = c32 * 32 + 8 * g + c;       // h=0; u2 = u1+4 (h=1)
#pragma unroll
        for (int rr2 = 0; rr2 < 2; rr2++) {
            const int r = half * 2 + rr2;
            const int t = r0 + r;
            const int w = c32 * 32 + 8 * c + 2 * ((g + t) & 3);
            const float* sp = sbuf + r * VROW + 3 * u1;
            const size_t o = (size_t)t * 512 + w;
            *(uint2*)&g_Vd[o]              = make_uint2(f2tf(sp[0]), f2tf(sp[12]));
            *(uint2*)&g_Vd[o + VPLANE]     = make_uint2(f2tf(sp[1]), f2tf(sp[13]));
            *(uint2*)&g_Vd[o + 2 * VPLANE] = make_uint2(f2tf(sp[2]), f2tf(sp[14]));
        }
    } else {
        // ---- W part: W1 [u][n] -> g_W1t[n][bu + permw(u%32, n)], 2 tiles per block
        float (*wt)[32][33] = reinterpret_cast<float (*)[32][33]>(sbuf);
        const int h = tid >> 8;                    // which tile
        const int t256 = tid & 255;
        const int tx = t256 & 31, ty = t256 >> 5;  // (32, 8)
        const int tile = (blockIdx.x - 2048) * 2 + h;
        const int bn = (tile & 15) * 32, bu = (tile >> 4) * 32;
#pragma unroll
        for (int j = 0; j < 32; j += 8)
            wt[h][ty + j][tx] = W1[(size_t)(bu + ty + j) * MULT + bn + tx];
        __syncthreads();
#pragma unroll
        for (int j = 0; j < 32; j += 8) {
            const int n = bn + ty + j;
            g_W1t[(size_t)n * 512 + bu + permw(tx, n)] = f2tf(wt[h][tx][ty + j]);
        }
    }
}

// ---- main fused kernel (R7 winner, unchanged): CTA 32x128, warp 16x32x3, 2 CTAs/SM
__global__ void __launch_bounds__(NTHR, 2)
fused(const float* __restrict__ S, const float* __restrict__ W0,
      float* __restrict__ out)
{
    extern __shared__ uint32_t dsm[];
    __shared__ float sS[96];
    __shared__ float sW0[384];

    const int tid  = threadIdx.x;
    const int lane = tid & 31;
    const int wid  = tid >> 5;
    const int q  = lane >> 2;          // 0..7
    const int rr = lane & 3;           // 0..3
    const int warp_t = wid >> 2;       // 0..1 -> rows warp_t*16
    const int warp_w = wid & 3;        // 0..3 -> cols warp_w*32
    const int bx = blockIdx.x, by = blockIdx.y;
    const int tt0 = by * BT, w0 = bx * BW;

    if (tid < 96)  sS[tid]  = S[(size_t)tt0 * 3 + tid];
    if (tid < 256) { sW0[tid] = W0[(tid >> 7) * 512 + w0 + (tid & 127)];
                     if (tid < 128) sW0[256 + tid] = W0[1024 + w0 + tid]; }

    // ---- cp.async staging addresses (loop-invariant)
    const uint32_t smem0 = smem_u32(dsm);
    uint32_t aDst[3]; const uint32_t* aSrc[3];
#pragma unroll
    for (int s = 0; s < 3; s++) {
        const int c = tid + s * NTHR;          // 0..767 (3 planes x 32 t x 8 chunks)
        const int i = c >> 8, rem = c & 255;
        const int t = rem >> 3, j = rem & 7;
        aDst[s] = smem0 + (i * (BT * 32) + t * 32 + 4 * j) * 4;
        aSrc[s] = g_Vd + (size_t)i * VPLANE + (size_t)(tt0 + t) * 512 + 4 * j;
    }
    uint32_t bDst[4]; const uint32_t* bSrc[4];
#pragma unroll
    for (int s = 0; s < 4; s++) {
        const int c = tid + s * NTHR;          // 0..1023 (128 n x 8 chunks)
        const int n = c >> 3, j = c & 7;
        bDst[s] = smem0 + (A_STAGE_W + n * 32 + 4 * j) * 4;
        bSrc[s] = g_W1t + (size_t)(w0 + n) * 512 + 4 * j;
    }

#define STAGE(K, BUF) do {                                                  \
        const uint32_t off_ = (BUF) * (STAGE_W * 4);                        \
        const int kw_ = (K) * 32;                                          \
        _Pragma("unroll")                                                   \
        for (int s_ = 0; s_ < 3; s_++) cpa16(aDst[s_] + off_, aSrc[s_] + kw_); \
        _Pragma("unroll")                                                   \
        for (int s_ = 0; s_ < 4; s_++) cpa16(bDst[s_] + off_, bSrc[s_] + kw_); \
        asm volatile("cp.async.commit_group;" ::: "memory");                \
    } while (0)

    float acc[3][4][4];
#pragma unroll
    for (int i = 0; i < 3; i++)
#pragma unroll
        for (int n = 0; n < 4; n++)
#pragma unroll
            for (int r = 0; r < 4; r++) acc[i][n][r] = 0.f;

    STAGE(0, 0);
    STAGE(1, 1);

    float4* out4 = reinterpret_cast<float4*>(out);
    const float4 zq = make_float4(0.f, 0.f, 0.f, 0.f);

    int buf = 0;
    for (int it = 0; it < NITER; ++it) {
        if (it == NITER - 1) asm volatile("cp.async.wait_group 0;" ::: "memory");
        else                 asm volatile("cp.async.wait_group 1;" ::: "memory");
        __syncthreads();

        if (it + 2 < NITER) {
            const int nb = (buf + 2 >= NSTAGE) ? buf + 2 - NSTAGE : buf + 2;
            STAGE(it + 2, nb);
        }

        // ---- stream the exact-zero block (2 rows x 384 quads per iter)
        {
            const int r = 2 * it + (tid >> 7);
            const int c = (tid & 127) * 3;
            float4* zp = out4 + (size_t)(tt0 + r) * 2048 + 512 + 384 * bx + c;
            zp[0] = zq; zp[1] = zq; zp[2] = zq;
        }

        // ---- compute 4 k8-steps (conflict-free LDS.64 everywhere)
        const uint32_t* sA = dsm + buf * STAGE_W;
        const uint32_t* sB = sA + A_STAGE_W;
        const int arow = (warp_t * 16 + q) * 32;
#pragma unroll
        for (int g = 0; g < 4; g++) {
            const int koff = 8 * rr + 2 * ((g + q) & 3);   // same for A rows & B cols
            uint32_t b[4][2];
#pragma unroll
            for (int nt = 0; nt < 4; nt++) {
                const int n = warp_w * 32 + nt * 8 + q;
                const uint2 bb = *reinterpret_cast<const uint2*>(&sB[n * 32 + koff]);
                b[nt][0] = bb.x; b[nt][1] = bb.y;     // k = 8g+rr, 8g+rr+4
            }
#pragma unroll
            for (int i = 0; i < 3; i++) {
                const uint32_t* ap = sA + i * (BT * 32) + arow + koff;
                const uint2 alo = *reinterpret_cast<const uint2*>(ap);        // row q
                const uint2 ahi = *reinterpret_cast<const uint2*>(ap + 256);  // row q+8
                uint32_t a[4] = {alo.x, ahi.x, alo.y, ahi.y};
#pragma unroll
                for (int nt = 0; nt < 4; nt++) mma8(acc[i][nt], a, b[nt]);
            }
        }
        buf = (buf + 1 >= NSTAGE) ? 0 : buf + 1;
    }

    // ---- epilogue: out1 (1o->1o), interleaved layout, vectorized float2
    const float sc = 0.04419417382415922f;  // 1/sqrt(512)
    {
        const int r  = tt0 + warp_t * 16 + q;
        const int wc = w0 + warp_w * 32 + 2 * rr;
#pragma unroll
        for (int nt = 0; nt < 4; nt++) {
            const int w = wc + nt * 8;
            float* p  = out + (size_t)r * OUTW + 512 + 3 * w;
            float* p2 = p + (size_t)8 * OUTW;
            float2 v;
            v = make_float2(acc[0][nt][0] * sc, acc[1][nt][0] * sc); *reinterpret_cast<float2*>(p + 0) = v;
            v = make_float2(acc[2][nt][0] * sc, acc[0][nt][1] * sc); *reinterpret_cast<float2*>(p + 2) = v;
            v = make_float2(acc[1][nt][1] * sc, acc[2][nt][1] * sc); *reinterpret_cast<float2*>(p + 4) = v;
            v = make_float2(acc[0][nt][2] * sc, acc[1][nt][2] * sc); *reinterpret_cast<float2*>(p2 + 0) = v;
            v = make_float2(acc[2][nt][2] * sc, acc[0][nt][3] * sc); *reinterpret_cast<float2*>(p2 + 2) = v;
            v = make_float2(acc[1][nt][3] * sc, acc[2][nt][3] * sc); *reinterpret_cast<float2*>(p2 + 4) = v;
        }
    }

    // ---- epilogue: out0 (0e->0e), cols [w0, w0+128)
    {
        const float k3 = 0.5773502691896258f;  // 1/sqrt(3)
        const int r  = tid >> 3;               // 0..31
        const int cb = (tid & 7) * 16;
        const float s0 = sS[r * 3 + 0], s1 = sS[r * 3 + 1], s2 = sS[r * 3 + 2];
        float* po = out + (size_t)(tt0 + r) * OUTW + w0 + cb;
#pragma unroll
        for (int jj = 0; jj < 16; jj += 4) {
            float4 v;
            v.x = (s0 * sW0[cb + jj + 0] + s1 * sW0[128 + cb + jj + 0] + s2 * sW0[256 + cb + jj + 0]) * k3;
            v.y = (s0 * sW0[cb + jj + 1] + s1 * sW0[128 + cb + jj + 1] + s2 * sW0[256 + cb + jj + 1]) * k3;
            v.z = (s0 * sW0[cb + jj + 2] + s1 * sW0[128 + cb + jj + 2] + s2 * sW0[256 + cb + jj + 2]) * k3;
            v.w = (s0 * sW0[cb + jj + 3] + s1 * sW0[128 + cb + jj + 3] + s2 * sW0[256 + cb + jj + 3]) * k3;
            *reinterpret_cast<float4*>(po + jj) = v;
        }
    }
}

extern "C" void kernel_launch(void* const* d_in, const int* in_sizes, int n_in,
                              void* d_out, int out_size) {
    const float* V  = nullptr;   // vectors [4,2048,1536] = 12582912
    const float* S  = nullptr;   // scalars [4,2048,3]    = 24576
    const float* W0 = nullptr;   // [3,512]               = 1536
    const float* W1 = nullptr;   // [512,512]             = 262144
    for (int i = 0; i < n_in; i++) {
        switch (in_sizes[i]) {
            case 12582912: V  = (const float*)d_in[i]; break;
            case 24576:    S  = (const float*)d_in[i]; break;
            case 1536:     W0 = (const float*)d_in[i]; break;
            case 262144:   W1 = (const float*)d_in[i]; break;
            default: break;
        }
    }
    float* out = (float*)d_out;

    pre_all<<<2176, 512>>>(V, W1);

    cudaFuncSetAttribute(fused, cudaFuncAttributeMaxDynamicSharedMemorySize, DYN_SMEM);
    dim3 grid(MULT / BW, T_TOT / BT);   // (4, 256) = 1024 CTAs
    fused<<<grid, NTHR, DYN_SMEM>>>(S, W0, out);
}